// round 3
// baseline (speedup 1.0000x reference)
#include <cuda_runtime.h>

#define BATCH 8
#define INPUT_SIZE 8192
#define HIDDEN_SIZE 8192
#define OUTPUT_SIZE 2048
#define KDIM 16384

#define SLICE  1024
#define SLICE4 (SLICE / 4)            // 256 float4 per batch per slice
#define NSPLIT1 (KDIM / SLICE)        // 16
#define NSPLIT2 (HIDDEN_SIZE / SLICE) // 8
#define TILES1 (HIDDEN_SIZE / 32)     // 256 row tiles (32 rows/block)
#define TILES2 (OUTPUT_SIZE / 16)     // 128 row tiles (16 rows/block)

typedef unsigned long long u64;

// Scratch (allocation-free): partial sums + hidden activations.
__device__ float g_part1[NSPLIT1][BATCH][HIDDEN_SIZE];  // 4 MB
__device__ float g_hidden[BATCH][HIDDEN_SIZE];          // 256 KB
__device__ float g_part2[NSPLIT2][BATCH][OUTPUT_SIZE];  // 512 KB

// --------------------------------------------------------------------------
// Packed dual-FMA:  d.lo += a.lo*b.lo ; d.hi += a.hi*b.hi
// --------------------------------------------------------------------------
__device__ __forceinline__ void fma2(u64& d, u64 a, u64 b) {
    asm("fma.rn.f32x2 %0, %1, %2, %0;" : "+l"(d) : "l"(a), "l"(b));
}
// 16B global load (streaming) into two packed u64
__device__ __forceinline__ void ldg_cs_u64x2(u64& a, u64& b, const void* p) {
    asm volatile("ld.global.cs.v2.u64 {%0,%1}, [%2];"
                 : "=l"(a), "=l"(b) : "l"(p));
}
__device__ __forceinline__ float pair_sum(u64 v) {
    return __uint_as_float((unsigned)v) + __uint_as_float((unsigned)(v >> 32));
}

// ==========================================================================
// Kernel 1: partial GEMV for pre-activation.
// Block = (tile, split): 32 weight rows x 1024 K-slice. 256 thr, 4 rows/warp.
// Stage input slice once, then barrier-free weight streaming.
// ==========================================================================
__global__ __launch_bounds__(256, 2)
void rnn_i2h_kernel(const float* __restrict__ x,
                    const float* __restrict__ h0,
                    const float* __restrict__ W)     // [HIDDEN, KDIM]
{
    __shared__ float4 s_in[BATCH][SLICE4];   // 32 KB

    const int tid   = threadIdx.x;
    const int lane  = tid & 31;
    const int warp  = tid >> 5;
    const int tile  = blockIdx.x & (TILES1 - 1);
    const int split = blockIdx.x >> 8;
    const int row0  = tile * 32 + warp * 4;

    // ---- stage input slice: 8 batches x 1024 floats ----------------------
    const float* src = (split < NSPLIT1 / 2)
                         ? (x  + split * SLICE)
                         : (h0 + (split - NSPLIT1 / 2) * SLICE);
    #pragma unroll
    for (int t = 0; t < 8; ++t) {
        int f  = tid + t * 256;
        int b  = f >> 8;                 // / SLICE4
        int k4 = f & (SLICE4 - 1);
        s_in[b][k4] = ((const float4*)(src + (size_t)b * INPUT_SIZE))[k4];
    }
    __syncthreads();        // the ONLY barrier

    u64 acc[4][BATCH];
    #pragma unroll
    for (int r = 0; r < 4; r++)
        #pragma unroll
        for (int b = 0; b < BATCH; b++)
            acc[r][b] = 0ull;           // two packed +0.0f

    const char* wp[4];
    #pragma unroll
    for (int r = 0; r < 4; r++)
        wp[r] = (const char*)(W + (size_t)(row0 + r) * KDIM + split * SLICE);

    #pragma unroll 2
    for (int i = 0; i < SLICE4 / 32; ++i) {      // 8 iterations
        const int k4 = i * 32 + lane;
        u64 w[4][2];
        #pragma unroll
        for (int r = 0; r < 4; r++)
            ldg_cs_u64x2(w[r][0], w[r][1], wp[r] + (size_t)k4 * 16);

        #pragma unroll
        for (int b = 0; b < BATCH; b++) {
            const u64* v = reinterpret_cast<const u64*>(&s_in[b][k4]);
            u64 v0 = v[0], v1 = v[1];
            #pragma unroll
            for (int r = 0; r < 4; r++) {
                fma2(acc[r][b], w[r][0], v0);
                fma2(acc[r][b], w[r][1], v1);
            }
        }
    }

    // ---- reduce within warp, write partials ------------------------------
    #pragma unroll
    for (int r = 0; r < 4; r++) {
        #pragma unroll
        for (int b = 0; b < BATCH; b++) {
            float s = pair_sum(acc[r][b]);
            #pragma unroll
            for (int off = 16; off > 0; off >>= 1)
                s += __shfl_xor_sync(0xffffffffu, s, off);
            if (lane == b)
                g_part1[split][b][row0 + r] = s;
        }
    }
}

// ==========================================================================
// Reduce 1: hidden = tanh(sum_{16 splits} part1 + bias)
// ==========================================================================
__global__ void rnn_reduce1_kernel(const float* __restrict__ bias)
{
    int idx = blockIdx.x * 256 + threadIdx.x;   // 65536
    int b = idx >> 13;
    int h = idx & (HIDDEN_SIZE - 1);
    float acc = __ldg(bias + h);
    #pragma unroll
    for (int s = 0; s < NSPLIT1; s++)
        acc += g_part1[s][b][h];
    g_hidden[b][h] = tanhf(acc);
}

// ==========================================================================
// Kernel 2: partial GEMV for output. 16 rows/block, 2 rows/warp, 8 K-splits.
// ==========================================================================
__global__ __launch_bounds__(256, 2)
void rnn_h2o_kernel(const float* __restrict__ W2)   // [OUT, HIDDEN]
{
    __shared__ float4 s_in[BATCH][SLICE4];   // 32 KB

    const int tid   = threadIdx.x;
    const int lane  = tid & 31;
    const int warp  = tid >> 5;
    const int tile  = blockIdx.x & (TILES2 - 1);
    const int split = blockIdx.x >> 7;
    const int row0  = tile * 16 + warp * 2;

    const float* src = &g_hidden[0][0] + split * SLICE;
    #pragma unroll
    for (int t = 0; t < 8; ++t) {
        int f  = tid + t * 256;
        int b  = f >> 8;
        int k4 = f & (SLICE4 - 1);
        s_in[b][k4] = ((const float4*)(src + (size_t)b * HIDDEN_SIZE))[k4];
    }
    __syncthreads();

    u64 acc[2][BATCH];
    #pragma unroll
    for (int r = 0; r < 2; r++)
        #pragma unroll
        for (int b = 0; b < BATCH; b++)
            acc[r][b] = 0ull;

    const char* wp[2];
    #pragma unroll
    for (int r = 0; r < 2; r++)
        wp[r] = (const char*)(W2 + (size_t)(row0 + r) * HIDDEN_SIZE + split * SLICE);

    #pragma unroll 4
    for (int i = 0; i < SLICE4 / 32; ++i) {      // 8 iterations
        const int k4 = i * 32 + lane;
        u64 w[2][2];
        #pragma unroll
        for (int r = 0; r < 2; r++)
            ldg_cs_u64x2(w[r][0], w[r][1], wp[r] + (size_t)k4 * 16);

        #pragma unroll
        for (int b = 0; b < BATCH; b++) {
            const u64* v = reinterpret_cast<const u64*>(&s_in[b][k4]);
            u64 v0 = v[0], v1 = v[1];
            #pragma unroll
            for (int r = 0; r < 2; r++) {
                fma2(acc[r][b], w[r][0], v0);
                fma2(acc[r][b], w[r][1], v1);
            }
        }
    }

    #pragma unroll
    for (int r = 0; r < 2; r++) {
        #pragma unroll
        for (int b = 0; b < BATCH; b++) {
            float s = pair_sum(acc[r][b]);
            #pragma unroll
            for (int off = 16; off > 0; off >>= 1)
                s += __shfl_xor_sync(0xffffffffu, s, off);
            if (lane == b)
                g_part2[split][b][row0 + r] = s;
        }
    }
}

// ==========================================================================
// Reduce 2: out = sum_{8 splits} part2 + bias2
// ==========================================================================
__global__ void rnn_reduce2_kernel(const float* __restrict__ bias2,
                                   float* __restrict__ out)
{
    int idx = blockIdx.x * 256 + threadIdx.x;   // 16384
    int b = idx >> 11;
    int o = idx & (OUTPUT_SIZE - 1);
    float acc = __ldg(bias2 + o);
    #pragma unroll
    for (int s = 0; s < NSPLIT2; s++)
        acc += g_part2[s][b][o];
    out[idx] = acc;
}

// --------------------------------------------------------------------------
// Inputs (metadata order): x, initial_hidden, i2h_weight, i2h_bias,
//                          h2o_weight, h2o_bias
// --------------------------------------------------------------------------
extern "C" void kernel_launch(void* const* d_in, const int* in_sizes, int n_in,
                              void* d_out, int out_size) {
    const float* x  = (const float*)d_in[0];
    const float* h0 = (const float*)d_in[1];
    const float* W1 = (const float*)d_in[2];
    const float* b1 = (const float*)d_in[3];
    const float* W2 = (const float*)d_in[4];
    const float* b2 = (const float*)d_in[5];
    float* out      = (float*)d_out;

    rnn_i2h_kernel<<<TILES1 * NSPLIT1, 256>>>(x, h0, W1);
    rnn_reduce1_kernel<<<(BATCH * HIDDEN_SIZE) / 256, 256>>>(b1);
    rnn_h2o_kernel<<<TILES2 * NSPLIT2, 256>>>(W2);
    rnn_reduce2_kernel<<<(BATCH * OUTPUT_SIZE) / 256, 256>>>(b2, out);
}

// round 4
// speedup vs baseline: 1.0232x; 1.0232x over previous
#include <cuda_runtime.h>

#define BATCH 8
#define INPUT_SIZE 8192
#define HIDDEN_SIZE 8192
#define OUTPUT_SIZE 2048
#define KDIM 16384

#define SLICE  1024
#define SLICE4 (SLICE / 4)            // 256 float4 per batch per slice
#define NSPLIT1 (KDIM / SLICE)        // 16
#define NSPLIT2 (HIDDEN_SIZE / SLICE) // 8
#define TILES1 (HIDDEN_SIZE / 32)     // 256 row tiles (32 rows/block)
#define TILES2 (OUTPUT_SIZE / 16)     // 128 row tiles (16 rows/block)
#define NITER  (SLICE4 / 32)          // 8 k-strips per slice

typedef unsigned long long u64;

// Scratch (allocation-free)
__device__ float g_part1[NSPLIT1][BATCH][HIDDEN_SIZE];  // 4 MB
__device__ float g_hidden[BATCH][HIDDEN_SIZE];          // 256 KB
__device__ float g_part2[NSPLIT2][BATCH][OUTPUT_SIZE];  // 512 KB

// --------------------------------------------------------------------------
__device__ __forceinline__ void fma2(u64& d, u64 a, u64 b) {
    asm("fma.rn.f32x2 %0, %1, %2, %0;" : "+l"(d) : "l"(a), "l"(b));
}
__device__ __forceinline__ void ldg_cs_u64x2(u64& a, u64& b, const void* p) {
    asm volatile("ld.global.cs.v2.u64 {%0,%1}, [%2];"
                 : "=l"(a), "=l"(b) : "l"(p));
}
__device__ __forceinline__ float pair_sum(u64 v) {
    return __uint_as_float((unsigned)v) + __uint_as_float((unsigned)(v >> 32));
}

// ==========================================================================
// Kernel 1: partial GEMV. Block = (tile, split): 32 rows x 1024-K slice.
// 256 thr, 4 rows/warp. Stage inputs once; weight stream is software-
// pipelined one iteration ahead in registers (loads always in flight).
// ==========================================================================
__global__ __launch_bounds__(256, 2)
void rnn_i2h_kernel(const float* __restrict__ x,
                    const float* __restrict__ h0,
                    const float* __restrict__ W)     // [HIDDEN, KDIM]
{
    __shared__ float4 s_in[BATCH][SLICE4];   // 32 KB

    const int tid   = threadIdx.x;
    const int lane  = tid & 31;
    const int warp  = tid >> 5;
    const int tile  = blockIdx.x & (TILES1 - 1);
    const int split = blockIdx.x >> 8;
    const int row0  = tile * 32 + warp * 4;

    // stage input slice (8 x 1024 floats)
    const float* src = (split < NSPLIT1 / 2)
                         ? (x  + split * SLICE)
                         : (h0 + (split - NSPLIT1 / 2) * SLICE);
    #pragma unroll
    for (int t = 0; t < 8; ++t) {
        int f  = tid + t * 256;
        int b  = f >> 8;
        int k4 = f & (SLICE4 - 1);
        s_in[b][k4] = ((const float4*)(src + (size_t)b * INPUT_SIZE))[k4];
    }
    __syncthreads();        // only barrier

    u64 acc[4][BATCH];
    #pragma unroll
    for (int r = 0; r < 4; r++)
        #pragma unroll
        for (int b = 0; b < BATCH; b++)
            acc[r][b] = 0ull;

    const char* wp[4];
    #pragma unroll
    for (int r = 0; r < 4; r++)
        wp[r] = (const char*)(W + (size_t)(row0 + r) * KDIM + split * SLICE);

    u64 w0[4][2], w1[4][2];

    auto ldw = [&](u64 (&wb)[4][2], int kk) {
        const size_t off = (size_t)(kk * 32 + lane) * 16;
        #pragma unroll
        for (int r = 0; r < 4; r++)
            ldg_cs_u64x2(wb[r][0], wb[r][1], wp[r] + off);
    };
    auto step = [&](u64 (&wb)[4][2], int kk) {
        const int k4v = kk * 32 + lane;
        #pragma unroll
        for (int b = 0; b < BATCH; b++) {
            const u64* v = reinterpret_cast<const u64*>(&s_in[b][k4v]);
            u64 va = v[0], vb = v[1];
            #pragma unroll
            for (int r = 0; r < 4; r++) {
                fma2(acc[r][b], wb[r][0], va);
                fma2(acc[r][b], wb[r][1], vb);
            }
        }
    };

    ldw(w0, 0);
    #pragma unroll
    for (int i = 0; i < NITER; i += 2) {
        ldw(w1, i + 1);          // prefetch next strip before computing
        step(w0, i);
        if (i + 2 < NITER) ldw(w0, i + 2);
        step(w1, i + 1);
    }

    #pragma unroll
    for (int r = 0; r < 4; r++) {
        #pragma unroll
        for (int b = 0; b < BATCH; b++) {
            float s = pair_sum(acc[r][b]);
            #pragma unroll
            for (int off = 16; off > 0; off >>= 1)
                s += __shfl_xor_sync(0xffffffffu, s, off);
            if (lane == b)
                g_part1[split][b][row0 + r] = s;
        }
    }
}

// ==========================================================================
// Reduce 1: hidden = tanh(sum_16 part1 + bias)   (float4 vectorized)
// ==========================================================================
__global__ void rnn_reduce1_kernel(const float* __restrict__ bias)
{
    int idx = blockIdx.x * 256 + threadIdx.x;       // 16384 float4s
    int b  = idx >> 11;                              // / (HIDDEN/4)
    int h4 = idx & (HIDDEN_SIZE / 4 - 1);
    float4 a = ((const float4*)bias)[h4];
    #pragma unroll
    for (int s = 0; s < NSPLIT1; s++) {
        float4 p = ((const float4*)&g_part1[s][b][0])[h4];
        a.x += p.x; a.y += p.y; a.z += p.z; a.w += p.w;
    }
    float4 r = make_float4(tanhf(a.x), tanhf(a.y), tanhf(a.z), tanhf(a.w));
    ((float4*)&g_hidden[b][0])[h4] = r;
}

// ==========================================================================
// Kernel 2: partial GEMV for output. 16 rows/block, 2 rows/warp, prefetched.
// ==========================================================================
__global__ __launch_bounds__(256, 2)
void rnn_h2o_kernel(const float* __restrict__ W2)   // [OUT, HIDDEN]
{
    __shared__ float4 s_in[BATCH][SLICE4];   // 32 KB

    const int tid   = threadIdx.x;
    const int lane  = tid & 31;
    const int warp  = tid >> 5;
    const int tile  = blockIdx.x & (TILES2 - 1);
    const int split = blockIdx.x >> 7;
    const int row0  = tile * 16 + warp * 2;

    const float* src = &g_hidden[0][0] + split * SLICE;
    #pragma unroll
    for (int t = 0; t < 8; ++t) {
        int f  = tid + t * 256;
        int b  = f >> 8;
        int k4 = f & (SLICE4 - 1);
        s_in[b][k4] = ((const float4*)(src + (size_t)b * HIDDEN_SIZE))[k4];
    }
    __syncthreads();

    u64 acc[2][BATCH];
    #pragma unroll
    for (int r = 0; r < 2; r++)
        #pragma unroll
        for (int b = 0; b < BATCH; b++)
            acc[r][b] = 0ull;

    const char* wp[2];
    #pragma unroll
    for (int r = 0; r < 2; r++)
        wp[r] = (const char*)(W2 + (size_t)(row0 + r) * HIDDEN_SIZE + split * SLICE);

    u64 w0[2][2], w1[2][2];

    auto ldw = [&](u64 (&wb)[2][2], int kk) {
        const size_t off = (size_t)(kk * 32 + lane) * 16;
        #pragma unroll
        for (int r = 0; r < 2; r++)
            ldg_cs_u64x2(wb[r][0], wb[r][1], wp[r] + off);
    };
    auto step = [&](u64 (&wb)[2][2], int kk) {
        const int k4v = kk * 32 + lane;
        #pragma unroll
        for (int b = 0; b < BATCH; b++) {
            const u64* v = reinterpret_cast<const u64*>(&s_in[b][k4v]);
            u64 va = v[0], vb = v[1];
            #pragma unroll
            for (int r = 0; r < 2; r++) {
                fma2(acc[r][b], wb[r][0], va);
                fma2(acc[r][b], wb[r][1], vb);
            }
        }
    };

    ldw(w0, 0);
    #pragma unroll
    for (int i = 0; i < NITER; i += 2) {
        ldw(w1, i + 1);
        step(w0, i);
        if (i + 2 < NITER) ldw(w0, i + 2);
        step(w1, i + 1);
    }

    #pragma unroll
    for (int r = 0; r < 2; r++) {
        #pragma unroll
        for (int b = 0; b < BATCH; b++) {
            float s = pair_sum(acc[r][b]);
            #pragma unroll
            for (int off = 16; off > 0; off >>= 1)
                s += __shfl_xor_sync(0xffffffffu, s, off);
            if (lane == b)
                g_part2[split][b][row0 + r] = s;
        }
    }
}

// ==========================================================================
// Reduce 2: out = sum_8 part2 + bias2   (float4 vectorized)
// ==========================================================================
__global__ void rnn_reduce2_kernel(const float* __restrict__ bias2,
                                   float* __restrict__ out)
{
    int idx = blockIdx.x * 128 + threadIdx.x;       // 4096 float4s
    int b  = idx >> 9;                               // / (OUT/4)
    int o4 = idx & (OUTPUT_SIZE / 4 - 1);
    float4 a = ((const float4*)bias2)[o4];
    #pragma unroll
    for (int s = 0; s < NSPLIT2; s++) {
        float4 p = ((const float4*)&g_part2[s][b][0])[o4];
        a.x += p.x; a.y += p.y; a.z += p.z; a.w += p.w;
    }
    ((float4*)out)[idx] = a;
}

// --------------------------------------------------------------------------
// Inputs: x, initial_hidden, i2h_weight, i2h_bias, h2o_weight, h2o_bias
// --------------------------------------------------------------------------
extern "C" void kernel_launch(void* const* d_in, const int* in_sizes, int n_in,
                              void* d_out, int out_size) {
    const float* x  = (const float*)d_in[0];
    const float* h0 = (const float*)d_in[1];
    const float* W1 = (const float*)d_in[2];
    const float* b1 = (const float*)d_in[3];
    const float* W2 = (const float*)d_in[4];
    const float* b2 = (const float*)d_in[5];
    float* out      = (float*)d_out;

    rnn_i2h_kernel<<<TILES1 * NSPLIT1, 256>>>(x, h0, W1);
    rnn_reduce1_kernel<<<(BATCH * HIDDEN_SIZE / 4) / 256, 256>>>(b1);
    rnn_h2o_kernel<<<TILES2 * NSPLIT2, 256>>>(W2);
    rnn_reduce2_kernel<<<(BATCH * OUTPUT_SIZE / 4) / 128, 128>>>(b2, out);
}